// round 17
// baseline (speedup 1.0000x reference)
#include <cuda_runtime.h>
#include <cuda_fp16.h>

#define N_NODES 50000
#define F 64
#define HDIM 128          // output cols of the dual GEMM (64 + 64)
#define BSTRIDE 128       // bucket region per node (4 reps x 32 cap)
#define BCAP 32
#define NREP 4

// Scratch: __device__ globals (allocation-free, graph-capturable).
// Invariants: g_cursor all-zero at kernel_launch entry (zero at module load;
// aggx_kernel re-zeroes after reading, every run). g_y row N_NODES is a
// dummy all-zero row (never written) used by padded lanes.
__device__ __align__(16) __half g_y[(size_t)(N_NODES + 1) * F]; // dinv[n]*x[n], fp16
__device__ __align__(16) __half g_a[(size_t)N_NODES * F];       // aggregated, fp16
__device__ __align__(16) uint4 g_wf[8 * 4 * 32];                // W MMA fragments
__device__ float g_dinv[N_NODES];
__device__ float g_invdeg[N_NODES];
__device__ __align__(16) int g_cursor[NREP * N_NODES];          // per (node, rep)
__device__ unsigned short g_srcs[(size_t)N_NODES * BSTRIDE];    // bucketed src ids (u16)

// ---------------------------------------------------------------------------
// Fused: blocks [0, nScatter) bucket-scatter edges (u16 payload); remaining
// blocks pre-pack W into per-lane MMA fragments (1024 entries, tiny).
// ---------------------------------------------------------------------------
__global__ void __launch_bounds__(256) scatter_wf_kernel(
    const int* __restrict__ ei, int E, int nScatter,
    const float* __restrict__ W1,
    const float* __restrict__ W2) {

    if ((int)blockIdx.x < nScatter) {
        int t = blockIdx.x * 256 + threadIdx.x;
        int rep = t & (NREP - 1);
        int base = t * 4;
        if (base + 4 <= E) {
            int4 s = *(const int4*)(ei + base);
            int4 d = *(const int4*)(ei + E + base);
            int p0 = atomicAdd(&g_cursor[d.x * NREP + rep], 1);
            int p1 = atomicAdd(&g_cursor[d.y * NREP + rep], 1);
            int p2 = atomicAdd(&g_cursor[d.z * NREP + rep], 1);
            int p3 = atomicAdd(&g_cursor[d.w * NREP + rep], 1);
            g_srcs[(size_t)d.x * BSTRIDE + rep * BCAP + p0] = (unsigned short)s.x;
            g_srcs[(size_t)d.y * BSTRIDE + rep * BCAP + p1] = (unsigned short)s.y;
            g_srcs[(size_t)d.z * BSTRIDE + rep * BCAP + p2] = (unsigned short)s.z;
            g_srcs[(size_t)d.w * BSTRIDE + rep * BCAP + p3] = (unsigned short)s.w;
        } else {
            for (int e = base; e < E; e++) {
                int d = ei[E + e];
                int pos = atomicAdd(&g_cursor[d * NREP + rep], 1);
                g_srcs[(size_t)d * BSTRIDE + rep * BCAP + pos] = (unsigned short)ei[e];
            }
        }
        return;
    }

    int p = (blockIdx.x - nScatter) * 256 + threadIdx.x;
    if (p < 8 * 4 * 32) {
        int lane = p & 31;
        int ks   = (p >> 5) & 3;
        int nt   = p >> 7;            // 0..7
        int g = lane >> 2, t = lane & 3;
        int c  = nt * 8 + g;          // W column (0..63)
        int k0 = ks * 16 + 2 * t;     // W row
        __half2 b0 = __floats2half2_rn(W1[(k0    ) * 64 + c], W1[(k0 + 1) * 64 + c]);
        __half2 b1 = __floats2half2_rn(W1[(k0 + 8) * 64 + c], W1[(k0 + 9) * 64 + c]);
        __half2 d0 = __floats2half2_rn(W2[(k0    ) * 64 + c], W2[(k0 + 1) * 64 + c]);
        __half2 d1 = __floats2half2_rn(W2[(k0 + 8) * 64 + c], W2[(k0 + 9) * 64 + c]);
        uint4 o = make_uint4(*reinterpret_cast<unsigned*>(&b0),
                             *reinterpret_cast<unsigned*>(&b1),
                             *reinterpret_cast<unsigned*>(&d0),
                             *reinterpret_cast<unsigned*>(&d1));
        g_wf[p] = o;
    }
}

// ---------------------------------------------------------------------------
// dinv + prescale: one warp per 2 nodes (half-warp per node).
// ---------------------------------------------------------------------------
__global__ void __launch_bounds__(256) dinv_y_kernel(const float* __restrict__ x) {
    int w    = (blockIdx.x * blockDim.x + threadIdx.x) >> 5;
    int lane = threadIdx.x & 31;
    int half = lane >> 4;
    int hl   = lane & 15;
    int node = w * 2 + half;
    if (node >= N_NODES) return;   // N_NODES even: warp-uniform exit

    float di;
    if (hl == 0) {
        int4 c = *(const int4*)(g_cursor + node * NREP);
        float dg = (float)(c.x + c.y + c.z + c.w + 1);   // +1 self loop
        di = rsqrtf(dg);
        g_dinv[node]   = di;
        g_invdeg[node] = 1.0f / dg;
    }
    di = __shfl_sync(0xffffffffu, di, half << 4);

    float4 v = *((const float4*)(x + (size_t)node * F) + hl);
    __half2 h0 = __floats2half2_rn(di * v.x, di * v.y);
    __half2 h1 = __floats2half2_rn(di * v.z, di * v.w);
    uint2 o = make_uint2(*reinterpret_cast<unsigned*>(&h0),
                         *reinterpret_cast<unsigned*>(&h1));
    *((uint2*)(g_y + (size_t)node * F) + hl) = o;
}

// ---------------------------------------------------------------------------
// Aggregate y (R15-verbatim): a[d] = dinv_d * (y_d + sum_src y_src) * invdeg_d.
// TWO nodes per warp; lane owns 4 cols (uint2). fp16x2 partials, 4-edge flush.
// Padded lanes point at the zero dummy row y[N_NODES].
// Re-zeroes cursors after reading (restores the entry invariant).
// ---------------------------------------------------------------------------
__global__ void __launch_bounds__(256) aggx_kernel() {
    int w    = (blockIdx.x * blockDim.x + threadIdx.x) >> 5;
    int lane = threadIdx.x & 31;
    int half = lane >> 4;
    int hl   = lane & 15;
    int node = w * 2 + half;
    if (node >= N_NODES) return;

    float di  = g_dinv[node];
    float inv = g_invdeg[node];
    int4 cc = *(const int4*)(g_cursor + node * NREP);
    if (hl == 0)
        *(int4*)(g_cursor + node * NREP) = make_int4(0, 0, 0, 0);
    int cnt_arr[4] = {cc.x, cc.y, cc.z, cc.w};

    float ax, ay, az, aw;
    {
        uint2 u = *((const uint2*)(g_y + (size_t)node * F) + hl);
        float2 f0 = __half22float2(*reinterpret_cast<__half2*>(&u.x));
        float2 f1 = __half22float2(*reinterpret_cast<__half2*>(&u.y));
        ax = f0.x; ay = f0.y; az = f1.x; aw = f1.y;
    }

    const __half2 z2 = __half2half2(__ushort_as_half(0));

    #pragma unroll
    for (int rep = 0; rep < NREP; rep++) {
        int cnt = cnt_arr[rep];
        const unsigned short* src = g_srcs + (size_t)node * BSTRIDE + rep * BCAP;

        int s_lo = N_NODES, s_hi = N_NODES;     // dummy zero row
        if (hl < cnt)      s_lo = src[hl];
        if (hl + 16 < cnt) s_hi = src[hl + 16];

        int nsub = (cnt + 7) >> 3;
        int nsub_other = __shfl_xor_sync(0xffffffffu, nsub, 16);
        int nsub_max = max(nsub, nsub_other);

        int selbase = half << 4;
        for (int sub = 0; sub < nsub_max; sub++) {
            int sv  = (sub < 2) ? s_lo : s_hi;
            int off = selbase + (sub & 1) * 8;
            #pragma unroll
            for (int grp = 0; grp < 2; grp++) {
                __half2 p0 = z2, p1 = z2;
                #pragma unroll
                for (int u2 = 0; u2 < 4; u2++) {
                    int ss = __shfl_sync(0xffffffffu, sv, off + grp * 4 + u2);
                    uint2 v = *((const uint2*)(g_y + (size_t)ss * F) + hl);
                    p0 = __hadd2(p0, *reinterpret_cast<__half2*>(&v.x));
                    p1 = __hadd2(p1, *reinterpret_cast<__half2*>(&v.y));
                }
                float2 f0 = __half22float2(p0);
                float2 f1 = __half22float2(p1);
                ax += f0.x; ay += f0.y; az += f1.x; aw += f1.y;
            }
        }
    }

    float s = di * inv;
    __half2 h0 = __floats2half2_rn(ax * s, ay * s);
    __half2 h1 = __floats2half2_rn(az * s, aw * s);
    uint2 o = make_uint2(*reinterpret_cast<unsigned*>(&h0),
                         *reinterpret_cast<unsigned*>(&h1));
    *((uint2*)(g_a + (size_t)node * F) + hl) = o;
}

// ---------------------------------------------------------------------------
// Fused dual-GEMM + epilogue, smem-free: out = relu(a@W1)*sigmoid(a@W2).
// 64-row tiles, 8 warps: warp = (rg 0..3, nh 0..1). A fragments are loaded
// DIRECTLY from g_a (L2-resident): 16 independent LDG.32 per thread, one
// 32B sector per (row, ks) across the warp. No smem, no staging, no barrier.
// B fragments from g_wf (one LDG.128 per (nt,ks)). Register-local epilogue.
// ---------------------------------------------------------------------------
__global__ void __launch_bounds__(256) gemm_epi_kernel(float* __restrict__ out) {
    int tid  = threadIdx.x;
    int row0 = blockIdx.x * 64;
    int warp = tid >> 5, lane = tid & 31;
    int rg = warp & 3;          // row group: rows rg*16 .. rg*16+15
    int nh = warp >> 2;         // nt half: nt = nh*4 .. nh*4+3
    int g = lane >> 2, t = lane & 3;

    int r1 = row0 + rg * 16 + g;
    int r2 = r1 + 8;
    // clamp read rows (stores are guarded; clamped values are never stored)
    const __half* a1 = g_a + (size_t)(r1 < N_NODES ? r1 : N_NODES - 1) * F;
    const __half* a2 = g_a + (size_t)(r2 < N_NODES ? r2 : N_NODES - 1) * F;

    unsigned afr[4][4];
    #pragma unroll
    for (int ks = 0; ks < 4; ks++) {
        int c0 = ks * 16 + 2 * t;
        afr[ks][0] = *(const unsigned*)(a1 + c0);
        afr[ks][1] = *(const unsigned*)(a2 + c0);
        afr[ks][2] = *(const unsigned*)(a1 + c0 + 8);
        afr[ks][3] = *(const unsigned*)(a2 + c0 + 8);
    }

    #pragma unroll
    for (int nt0 = 0; nt0 < 4; nt0++) {
        int nt = nh * 4 + nt0;
        const uint4* wf = g_wf + (nt * 4) * 32 + lane;
        float c1[4] = {0.f, 0.f, 0.f, 0.f};   // layer1 (cols nt*8..)
        float c2[4] = {0.f, 0.f, 0.f, 0.f};   // layer2 (cols 64+nt*8..)
        #pragma unroll
        for (int ks = 0; ks < 4; ks++) {
            uint4 f = wf[ks * 32];
            asm volatile(
                "mma.sync.aligned.m16n8k16.row.col.f32.f16.f16.f32 "
                "{%0,%1,%2,%3}, {%4,%5,%6,%7}, {%8,%9}, {%0,%1,%2,%3};"
                : "+f"(c1[0]), "+f"(c1[1]), "+f"(c1[2]), "+f"(c1[3])
                : "r"(afr[ks][0]), "r"(afr[ks][1]), "r"(afr[ks][2]), "r"(afr[ks][3]),
                  "r"(f.x), "r"(f.y));
            asm volatile(
                "mma.sync.aligned.m16n8k16.row.col.f32.f16.f16.f32 "
                "{%0,%1,%2,%3}, {%4,%5,%6,%7}, {%8,%9}, {%0,%1,%2,%3};"
                : "+f"(c2[0]), "+f"(c2[1]), "+f"(c2[2]), "+f"(c2[3])
                : "r"(afr[ks][0]), "r"(afr[ks][1]), "r"(afr[ks][2]), "r"(afr[ks][3]),
                  "r"(f.z), "r"(f.w));
        }

        int col = nt * 8 + 2 * t;
        if (r1 < N_NODES) {
            float2 o;
            o.x = fmaxf(c1[0], 0.0f) * __fdividef(1.0f, 1.0f + __expf(-c2[0]));
            o.y = fmaxf(c1[1], 0.0f) * __fdividef(1.0f, 1.0f + __expf(-c2[1]));
            *(float2*)(out + (size_t)r1 * F + col) = o;
        }
        if (r2 < N_NODES) {
            float2 o;
            o.x = fmaxf(c1[2], 0.0f) * __fdividef(1.0f, 1.0f + __expf(-c2[2]));
            o.y = fmaxf(c1[3], 0.0f) * __fdividef(1.0f, 1.0f + __expf(-c2[3]));
            *(float2*)(out + (size_t)r2 * F + col) = o;
        }
    }
}

// ---------------------------------------------------------------------------
extern "C" void kernel_launch(void* const* d_in, const int* in_sizes, int n_in,
                              void* d_out, int out_size) {
    const float* x  = (const float*)d_in[0];
    const int*   ei = (const int*)d_in[1];   // int32 (JAX x64 disabled)
    const float* W1 = (const float*)d_in[2];
    const float* W2 = (const float*)d_in[3];
    float* out = (float*)d_out;

    int E  = in_sizes[1] / 2;
    int T4 = (E + 3) / 4;
    int S  = (T4 + 255) / 256;                 // scatter blocks (first)
    int Wb = (8 * 4 * 32 + 255) / 256;         // W-fragment pack blocks

    scatter_wf_kernel<<<S + Wb, 256>>>(ei, E, S, W1, W2);
    dinv_y_kernel<<<(N_NODES / 2 * 32 + 255) / 256, 256>>>(x);
    aggx_kernel<<<(N_NODES / 2 * 32 + 255) / 256, 256>>>();   // 2 nodes per warp
    gemm_epi_kernel<<<(N_NODES + 63) / 64, 256>>>(out);
}